// round 13
// baseline (speedup 1.0000x reference)
#include <cuda_runtime.h>
#include <cuda_fp16.h>

// FixedFoveatedSensor: out[b,c,h,w] = sum_s bilinear(img, warp(pos_s)) * det_s / sum_s det_s
// img: (4,3,1024,1024) f32, t: (1,) f32, jitter: (16,256,256,2) f32, out: (4,3,256,256) f32
//
// Stage: planar fp32 -> flat interleaved fp16 buffers b0 (ch0-7, 16B/px), b1 (ch8-11, 8B/px).
// Gather: block = 16 sensor px (one row segment) x 16 spp. The tanh warp is monotonic, so
// the block's source footprint is a rectangle computed in closed form from the 4 extreme
// positions (<= ~92 x 8 records at t=1). The tile is loaded coalesced into shared memory,
// and all bilinear sampling happens via LDS — zero gather wavefronts in L1tex.
// The reduction buffer aliases the tile memory (tile dead before partials staged).

#define SPP 16
#define SH 256
#define SW 256
#define NBC 12
#define NVALS 13
#define PIX_PER_BLOCK 16
#define BLOCK 256
#define IMG_H 1024
#define IMG_W 1024
#define NPIX (IMG_H * IMG_W)
#define MAXREC 1280                    // tile capacity (records); worst case at t=1 is ~736

__device__ uint4 g_b0[NPIX];   // 16 MB: ch0-7 fp16
__device__ uint2 g_b1[NPIX];   // 8 MB:  ch8-11 fp16

// ---------------- stage: 4 pixels per thread ----------------
__global__ __launch_bounds__(256)
void stage_kernel(const float* __restrict__ img)
{
    const int px0 = (blockIdx.x * 256 + threadIdx.x) * 4;

    float4 v[NBC];
#pragma unroll
    for (int c = 0; c < NBC; c++)
        v[c] = *reinterpret_cast<const float4*>(img + (size_t)c * NPIX + px0);

    const float* f = reinterpret_cast<const float*>(v);

#pragma unroll
    for (int k = 0; k < 4; k++) {
        unsigned u0[4], u1[2];
#pragma unroll
        for (int q = 0; q < 4; q++) {
            const __half2 h = __floats2half2_rn(f[(2 * q) * 4 + k], f[(2 * q + 1) * 4 + k]);
            u0[q] = *reinterpret_cast<const unsigned*>(&h);
        }
#pragma unroll
        for (int q = 0; q < 2; q++) {
            const __half2 h = __floats2half2_rn(f[(8 + 2 * q) * 4 + k], f[(9 + 2 * q) * 4 + k]);
            u1[q] = *reinterpret_cast<const unsigned*>(&h);
        }
        g_b0[px0 + k] = make_uint4(u0[0], u0[1], u0[2], u0[3]);
        g_b1[px0 + k] = make_uint2(u1[0], u1[1]);
    }
}

// ---------------- gather ----------------
__device__ __forceinline__ float warp_to_gx(float pos, float tt, float s_inv, float scale)
{
    const float wr = tanhf(tt * pos) * s_inv;
    float g = (wr + 1.0f) * scale - 0.5f;
    return fminf(fmaxf(g, 0.0f), 2.0f * scale - 1.0f);
}

__global__ __launch_bounds__(BLOCK)
void ffs_kernel(const float* __restrict__ t,
                const float* __restrict__ jitter,
                float* __restrict__ out)
{
    __shared__ float2 jit_s[SPP][PIX_PER_BLOCK + 1];
    __shared__ float  det_s[PIX_PER_BLOCK];
    __shared__ __align__(16) char tile_raw[MAXREC * 24];      // 30720 B
    uint4* __restrict__ tA = reinterpret_cast<uint4*>(tile_raw);                 // 20480 B
    uint2* __restrict__ tB = reinterpret_cast<uint2*>(tile_raw + MAXREC * 16);   // 10240 B
    float* __restrict__ red = reinterpret_cast<float*>(tile_raw);                // aliases tile (phase 2)

    const int tid = threadIdx.x;
    const int pixelBase = blockIdx.x * PIX_PER_BLOCK;

    // coalesced jitter load
    {
        const int s = tid >> 4;
        const int p = tid & 15;
        jit_s[s][p] = ((const float2*)jitter)[(size_t)s * (SH * SW) + pixelBase + p];
    }

    const int spp = tid & 15;
    const int pin = tid >> 4;
    const int pixel = pixelBase + pin;
    const int h = pixel >> 8;
    const int w = pixel & 255;

    const float tt    = t[0];
    const float s_inv = 1.0f / tanhf(tt);
    const float step  = 2.0f / 256.0f;

    // ---- block-uniform tile bounds (monotonic warp => use extreme positions) ----
    const int w0 = pixelBase & 255;
    const float px_min = -1.0f + (float)w0 * step;
    const float px_max = -1.0f + (float)(w0 + PIX_PER_BLOCK) * step;
    const float py_min = -1.0f + (float)h * step;
    const float py_max = -1.0f + (float)(h + 1) * step;

    const int x_min = (int)floorf(warp_to_gx(px_min, tt, s_inv, 512.0f));
    const int x_max = min((int)floorf(warp_to_gx(px_max, tt, s_inv, 512.0f)) + 1, IMG_W - 1);
    const int y_min = (int)floorf(warp_to_gx(py_min, tt, s_inv, 512.0f));
    const int y_max = min((int)floorf(warp_to_gx(py_max, tt, s_inv, 512.0f)) + 1, IMG_H - 1);
    const int tile_w = x_max - x_min + 1;
    const int tile_h = y_max - y_min + 1;
    const int nrec = min(tile_w * tile_h, MAXREC);

    __syncthreads();   // jit_s ready; also nothing writes tile before this

    // ---- cooperative tile fill (coalesced in x) ----
    for (int i = tid; i < nrec; i += BLOCK) {
        const int ry = i / tile_w;
        const int rx = i - ry * tile_w;
        const int g = (y_min + ry) * IMG_W + (x_min + rx);
        tA[i] = g_b0[g];
        tB[i] = g_b1[g];
    }

    // ---- per-thread sample coordinates ----
    const float2 jit = jit_s[spp][pin];
    const float posx = fmaf(jit.x, step, -1.0f + (float)w * step);
    const float posy = fmaf(jit.y, step, -1.0f + (float)h * step);

    const float thx = tanhf(tt * posx);
    const float thy = tanhf(tt * posy);
    const float ddx = tt * (1.0f - thx * thx) * s_inv;
    const float ddy = tt * (1.0f - thy * thy) * s_inv;
    const float det = ddx * ddy;

    float gx = (thx * s_inv + 1.0f) * 512.0f - 0.5f;
    float gy = (thy * s_inv + 1.0f) * 512.0f - 0.5f;
    gx = fminf(fmaxf(gx, 0.0f), (float)(IMG_W - 1));
    gy = fminf(fmaxf(gy, 0.0f), (float)(IMG_H - 1));
    const float x0f = floorf(gx);
    const float y0f = floorf(gy);
    const float fx = gx - x0f;
    const float fy = gy - y0f;
    const int x0 = (int)x0f;
    const int y0 = (int)y0f;
    const int x1 = min(x0 + 1, IMG_W - 1);
    const int y1 = min(y0 + 1, IMG_H - 1);

    const float w11 = fx * fy * det;
    const float w01 = fx * det - w11;
    const float w10 = fy * det - w11;
    const float w00 = det - w01 - w10 - w11;

    __syncthreads();   // tile filled

    // ---- sample from shared tile ----
    const int r0 = (y0 - y_min) * tile_w;
    const int r1 = (y1 - y_min) * tile_w;
    const int c0 = x0 - x_min;
    const int c1 = x1 - x_min;

    float acc[NBC];
#pragma unroll
    for (int j = 0; j < NBC; j++) acc[j] = 0.0f;

    {
        const int   ii[4] = { r0 + c0, r0 + c1, r1 + c0, r1 + c1 };
        const float ww[4] = { w00, w01, w10, w11 };
#pragma unroll
        for (int c = 0; c < 4; c++) {
            const uint4 a = tA[ii[c]];
            const uint2 b = tB[ii[c]];
            const unsigned uu[6] = { a.x, a.y, a.z, a.w, b.x, b.y };
            const float wc = ww[c];
#pragma unroll
            for (int q = 0; q < 6; q++) {
                const float2 f = __half22float2(*reinterpret_cast<const __half2*>(&uu[q]));
                acc[2 * q]     = fmaf(f.x, wc, acc[2 * q]);
                acc[2 * q + 1] = fmaf(f.y, wc, acc[2 * q + 1]);
            }
        }
    }

    __syncthreads();   // all tile reads done; red may alias tile now

#pragma unroll
    for (int j = 0; j < NBC; j++) red[tid * NVALS + j] = acc[j];
    red[tid * NVALS + NBC] = det;
    __syncthreads();

    float sum = 0.0f;
    int p = 0, j = 0;
    if (tid < PIX_PER_BLOCK * NVALS) {
        p = tid / NVALS;
        j = tid - p * NVALS;
        const float* b2 = red + (p * SPP) * NVALS + j;
#pragma unroll
        for (int k = 0; k < SPP; k++) sum += b2[k * NVALS];
        if (j == NBC) det_s[p] = sum;
    }
    __syncthreads();

    if (tid < PIX_PER_BLOCK * NVALS && j < NBC) {
        const int opix = pixelBase + p;
        out[(size_t)j * (SH * SW) + opix] = sum / det_s[p];
    }
}

extern "C" void kernel_launch(void* const* d_in, const int* in_sizes, int n_in,
                              void* d_out, int out_size)
{
    const float* img    = (const float*)d_in[0];
    const float* t      = (const float*)d_in[1];
    const float* jitter = (const float*)d_in[2];
    float* out          = (float*)d_out;

    stage_kernel<<<NPIX / (256 * 4), 256>>>(img);
    ffs_kernel<<<(SH * SW) / PIX_PER_BLOCK, BLOCK>>>(t, jitter, out);
}